// round 6
// baseline (speedup 1.0000x reference)
#include <cuda_runtime.h>
#include <cuda_bf16.h>

#define Nn 8192
#define Ff 1024
#define Fk 64
#define Hh 4
#define Cc 256
#define MAXN 128
#define LEAKY 0.2f

// ---- scratch (static device globals: allocation-free) ----
__device__ float    g_feats[(size_t)Nn * Cc];   // 8 MB
__device__ float    g_ss[Hh * Nn];
__device__ float    g_sn[Hh * Nn];
__device__ int      g_nbr[Nn * MAXN];
__device__ int      g_deg[Nn];
__device__ unsigned g_Whi[(size_t)Cc * Ff / 2]; // W transposed to [n=(h,k)][f], bf16 pairs
__device__ unsigned g_Wlo[(size_t)Cc * Ff / 2];

// ============================================================================
// bf16 hi/lo split helpers
// ============================================================================
__device__ __forceinline__ void split2(float a, float b, unsigned& hi, unsigned& lo) {
    __nv_bfloat16 ha = __float2bfloat16(a), hb = __float2bfloat16(b);
    __nv_bfloat16 la = __float2bfloat16(a - __bfloat162float(ha));
    __nv_bfloat16 lb = __float2bfloat16(b - __bfloat162float(hb));
    hi = (unsigned)__bfloat16_as_ushort(ha) | ((unsigned)__bfloat16_as_ushort(hb) << 16);
    lo = (unsigned)__bfloat16_as_ushort(la) | ((unsigned)__bfloat16_as_ushort(lb) << 16);
}

__global__ __launch_bounds__(256) void convert_w(const float* __restrict__ W) {
    int idx = blockIdx.x * 256 + threadIdx.x;   // 0..131071 = 256 n-rows x 512 pairs
    int n = idx >> 9;
    int f2 = idx & 511;
    int h = n >> 6, k = n & 63;
    const float* base = W + (size_t)h * (Ff * Fk) + k;
    float a = base[(size_t)(2 * f2) * Fk];
    float b = base[(size_t)(2 * f2 + 1) * Fk];
    unsigned hi, lo;
    split2(a, b, hi, lo);
    g_Whi[idx] = hi;
    g_Wlo[idx] = lo;
}

// ============================================================================
// Tensor-core GEMM via mma.sync (baseline PTX path).
// feats[8192 x 256] = X[8192 x 1024] * Wt[1024 x 256], 3-term bf16 split.
// CTA: 128m x 128n, K chunks of 64, 256 thr (8 warps, 4m x 2n), warp 32x64.
// ============================================================================
#define TP   144           // padded row pitch (bytes) for 64 bf16 = 128B data
#define TSZ  (128 * TP)    // 18432
#define BUFSZ (4 * TSZ)    // 73728
#define SMEM_DYN (2 * BUFSZ)

__device__ __forceinline__ void mma16816(float* d, const unsigned* a, const unsigned* b) {
    asm volatile(
        "mma.sync.aligned.m16n8k16.row.col.f32.bf16.bf16.f32 "
        "{%0,%1,%2,%3}, {%4,%5,%6,%7}, {%8,%9}, {%0,%1,%2,%3};"
        : "+f"(d[0]), "+f"(d[1]), "+f"(d[2]), "+f"(d[3])
        : "r"(a[0]), "r"(a[1]), "r"(a[2]), "r"(a[3]), "r"(b[0]), "r"(b[1]));
}

__global__ __launch_bounds__(256) void gemm_kernel(const float* __restrict__ X) {
    extern __shared__ char dyn[];
    const int t = threadIdx.x;
    const int w = t >> 5, lane = t & 31;
    const int bm = blockIdx.x * 128;
    const int n0 = blockIdx.y * 128;
    const int mrow = (w & 3) * 32;     // warp m-offset
    const int ncol = (w >> 2) * 64;    // warp n-offset
    const int r  = lane >> 2;          // fragment group row
    const int cb = (lane & 3) * 2;     // fragment k pair base

    float acc[2][8][4];
#pragma unroll
    for (int a = 0; a < 2; a++)
#pragma unroll
        for (int b = 0; b < 8; b++)
#pragma unroll
            for (int q = 0; q < 4; q++) acc[a][b][q] = 0.f;

    const uint4* WhiG = (const uint4*)g_Whi;
    const uint4* WloG = (const uint4*)g_Wlo;

    float4 xr[8];
    uint4  whr[4], wlr[4];

    // ---- prologue: load chunk 0 ----
#pragma unroll
    for (int i = 0; i < 8; i++) {
        int u = t + i * 256, row = u >> 4, j = u & 15;
        xr[i] = *(const float4*)(X + (size_t)(bm + row) * Ff + j * 4);
    }
#pragma unroll
    for (int i = 0; i < 4; i++) {
        int u = t + i * 256, row = u >> 3, j = u & 7;
        size_t g = (size_t)(n0 + row) * 128 + j;
        whr[i] = WhiG[g];
        wlr[i] = WloG[g];
    }
    {
        char* buf = dyn;
#pragma unroll
        for (int i = 0; i < 8; i++) {
            int u = t + i * 256, row = u >> 4, j = u & 15;
            uint2 h, l;
            split2(xr[i].x, xr[i].y, h.x, l.x);
            split2(xr[i].z, xr[i].w, h.y, l.y);
            *(uint2*)(buf + row * TP + j * 8)       = h;
            *(uint2*)(buf + TSZ + row * TP + j * 8) = l;
        }
#pragma unroll
        for (int i = 0; i < 4; i++) {
            int u = t + i * 256, row = u >> 3, j = u & 7;
            *(uint4*)(buf + 2 * TSZ + row * TP + j * 16) = whr[i];
            *(uint4*)(buf + 3 * TSZ + row * TP + j * 16) = wlr[i];
        }
    }
    __syncthreads();

#pragma unroll 1
    for (int c = 0; c < 16; c++) {
        // ---- issue global loads for next chunk ----
        if (c < 15) {
#pragma unroll
            for (int i = 0; i < 8; i++) {
                int u = t + i * 256, row = u >> 4, j = u & 15;
                xr[i] = *(const float4*)(X + (size_t)(bm + row) * Ff + (c + 1) * 64 + j * 4);
            }
#pragma unroll
            for (int i = 0; i < 4; i++) {
                int u = t + i * 256, row = u >> 3, j = u & 7;
                size_t g = (size_t)(n0 + row) * 128 + (c + 1) * 8 + j;
                whr[i] = WhiG[g];
                wlr[i] = WloG[g];
            }
        }

        // ---- mma on current buffer ----
        {
            char* buf = dyn + (c & 1) * BUFSZ;
            char* Ahi = buf;
            char* Alo = buf + TSZ;
            char* Bhi = buf + 2 * TSZ;
            char* Blo = buf + 3 * TSZ;
#pragma unroll
            for (int ks = 0; ks < 4; ks++) {
                unsigned afh[2][4], afl[2][4];   // [mb][reg]
                unsigned bfh[8][2], bfl[8][2];   // [nb][reg]
#pragma unroll
                for (int mb = 0; mb < 2; mb++) {
                    int ab = (mrow + mb * 16 + r) * TP + (ks * 16 + cb) * 2;
                    afh[mb][0] = *(const unsigned*)(Ahi + ab);
                    afh[mb][1] = *(const unsigned*)(Ahi + ab + 8 * TP);
                    afh[mb][2] = *(const unsigned*)(Ahi + ab + 16);
                    afh[mb][3] = *(const unsigned*)(Ahi + ab + 8 * TP + 16);
                    afl[mb][0] = *(const unsigned*)(Alo + ab);
                    afl[mb][1] = *(const unsigned*)(Alo + ab + 8 * TP);
                    afl[mb][2] = *(const unsigned*)(Alo + ab + 16);
                    afl[mb][3] = *(const unsigned*)(Alo + ab + 8 * TP + 16);
                }
#pragma unroll
                for (int nb = 0; nb < 8; nb++) {
                    int bb = (ncol + nb * 8 + r) * TP + (ks * 16 + cb) * 2;
                    bfh[nb][0] = *(const unsigned*)(Bhi + bb);
                    bfh[nb][1] = *(const unsigned*)(Bhi + bb + 16);
                    bfl[nb][0] = *(const unsigned*)(Blo + bb);
                    bfl[nb][1] = *(const unsigned*)(Blo + bb + 16);
                }
#pragma unroll
                for (int mb = 0; mb < 2; mb++)
#pragma unroll
                    for (int nb = 0; nb < 8; nb++) {
                        mma16816(acc[mb][nb], afh[mb], bfh[nb]);
                        mma16816(acc[mb][nb], afh[mb], bfl[nb]);
                        mma16816(acc[mb][nb], afl[mb], bfh[nb]);
                    }
            }
        }

        // ---- store next chunk into other buffer ----
        if (c < 15) {
            char* buf = dyn + ((c + 1) & 1) * BUFSZ;
#pragma unroll
            for (int i = 0; i < 8; i++) {
                int u = t + i * 256, row = u >> 4, j = u & 15;
                uint2 h, l;
                split2(xr[i].x, xr[i].y, h.x, l.x);
                split2(xr[i].z, xr[i].w, h.y, l.y);
                *(uint2*)(buf + row * TP + j * 8)       = h;
                *(uint2*)(buf + TSZ + row * TP + j * 8) = l;
            }
#pragma unroll
            for (int i = 0; i < 4; i++) {
                int u = t + i * 256, row = u >> 3, j = u & 7;
                *(uint4*)(buf + 2 * TSZ + row * TP + j * 16) = whr[i];
                *(uint4*)(buf + 3 * TSZ + row * TP + j * 16) = wlr[i];
            }
            __syncthreads();
        }
    }

    // ---- epilogue: write accumulators ----
#pragma unroll
    for (int mb = 0; mb < 2; mb++) {
        int row0 = bm + mrow + mb * 16 + r;
#pragma unroll
        for (int nb = 0; nb < 8; nb++) {
            int col = n0 + ncol + nb * 8 + cb;
            *(float2*)(g_feats + (size_t)row0 * Cc + col) =
                make_float2(acc[mb][nb][0], acc[mb][nb][1]);
            *(float2*)(g_feats + (size_t)(row0 + 8) * Cc + col) =
                make_float2(acc[mb][nb][2], acc[mb][nb][3]);
        }
    }
}

// ============================================================================
// s_self / s_neigh: one warp per (n,h) — coalesced 256B row read + shfl reduce
// grid = 4096 x 256 (32768 warps)
// ============================================================================
__global__ __launch_bounds__(256) void s_kernel(const float* __restrict__ attn_a) {
    int wi = (blockIdx.x * 256 + threadIdx.x) >> 5;   // 0..32767
    int lane = threadIdx.x & 31;
    int h = wi & 3, n = wi >> 2;
    const float* fp = g_feats + (size_t)n * Cc + h * Fk;
    float f0 = fp[lane];
    float f1 = fp[lane + 32];
    const float* av = attn_a + h * 2 * Fk;
    float ss = f0 * __ldg(av + lane)      + f1 * __ldg(av + lane + 32);
    float sn = f0 * __ldg(av + 64 + lane) + f1 * __ldg(av + 96 + lane);
#pragma unroll
    for (int o = 16; o; o >>= 1) {
        ss += __shfl_xor_sync(0xffffffffu, ss, o);
        sn += __shfl_xor_sync(0xffffffffu, sn, o);
    }
    if (lane == 0) {
        g_ss[h * Nn + n] = ss;
        g_sn[h * Nn + n] = sn;
    }
}

// ============================================================================
// Adjacency build (runs on side stream, overlapped with GEMM chain)
// ============================================================================
__global__ __launch_bounds__(256) void adj_kernel(const float* __restrict__ A) {
    int row = blockIdx.x;
    __shared__ int cnt;
    if (threadIdx.x == 0) cnt = 0;
    __syncthreads();
    const float4* ap = (const float4*)(A + (size_t)row * Nn);
    for (int c4 = threadIdx.x; c4 < Nn / 4; c4 += 256) {
        float4 v = ap[c4];
        int base = c4 * 4;
        if (v.x != 0.f) { int p = atomicAdd(&cnt, 1); if (p < MAXN) g_nbr[row * MAXN + p] = base; }
        if (v.y != 0.f) { int p = atomicAdd(&cnt, 1); if (p < MAXN) g_nbr[row * MAXN + p] = base + 1; }
        if (v.z != 0.f) { int p = atomicAdd(&cnt, 1); if (p < MAXN) g_nbr[row * MAXN + p] = base + 2; }
        if (v.w != 0.f) { int p = atomicAdd(&cnt, 1); if (p < MAXN) g_nbr[row * MAXN + p] = base + 3; }
    }
    __syncthreads();
    if (threadIdx.x == 0) g_deg[row] = min(cnt, MAXN);
}

// ============================================================================
// Aggregation: sparse softmax + gather + ReLU
// ============================================================================
__global__ __launch_bounds__(128) void agg_kernel(const float* __restrict__ bias,
                                                  float* __restrict__ out) {
    int i = blockIdx.x;
    int tid = threadIdx.x;
    int h = tid >> 5, lane = tid & 31;
    __shared__ int   snbr[MAXN];
    __shared__ float sw[Hh][MAXN];

    int d = g_deg[i];
    for (int j = tid; j < d; j += 128) snbr[j] = g_nbr[i * MAXN + j];
    __syncthreads();

    float si = g_ss[h * Nn + i];
    float e[4];
    float mx = -1e30f;
#pragma unroll
    for (int r = 0; r < 4; r++) {
        int j = lane + r * 32;
        if (j < d) {
            float sc = si + g_sn[h * Nn + snbr[j]];
            sc = sc > 0.f ? sc : LEAKY * sc;
            e[r] = sc;
            mx = fmaxf(mx, sc);
        } else {
            e[r] = -1e30f;
        }
    }
#pragma unroll
    for (int o = 16; o; o >>= 1) mx = fmaxf(mx, __shfl_xor_sync(0xffffffffu, mx, o));

    float sum = 0.f;
#pragma unroll
    for (int r = 0; r < 4; r++) {
        int j = lane + r * 32;
        if (j < d) {
            float w = __expf(e[r] - mx);
            sw[h][j] = w;
            sum += w;
        }
    }
#pragma unroll
    for (int o = 16; o; o >>= 1) sum += __shfl_xor_sync(0xffffffffu, sum, o);
    __syncwarp();

    float inv = 1.0f / sum;
    float acc0 = 0.f, acc1 = 0.f;
    int j = 0;
    for (; j + 2 <= d; j += 2) {
        float w0 = sw[h][j], w1 = sw[h][j + 1];
        const float* f0 = g_feats + (size_t)snbr[j] * Cc + h * Fk;
        const float* f1 = g_feats + (size_t)snbr[j + 1] * Cc + h * Fk;
        float a00 = f0[lane], a01 = f0[lane + 32];
        float a10 = f1[lane], a11 = f1[lane + 32];
        acc0 += w0 * a00 + w1 * a10;
        acc1 += w0 * a01 + w1 * a11;
    }
    if (j < d) {
        float w0 = sw[h][j];
        const float* f0 = g_feats + (size_t)snbr[j] * Cc + h * Fk;
        acc0 += w0 * f0[lane];
        acc1 += w0 * f0[lane + 32];
    }
    float b0 = bias[h * Fk + lane];
    float b1 = bias[h * Fk + lane + 32];
    out[(size_t)i * Cc + h * Fk + lane]      = fmaxf(acc0 * inv + b0, 0.f);
    out[(size_t)i * Cc + h * Fk + lane + 32] = fmaxf(acc1 * inv + b1, 0.f);
}

// ============================================================================
extern "C" void kernel_launch(void* const* d_in, const int* in_sizes, int n_in,
                              void* d_out, int out_size) {
    const float* X      = (const float*)d_in[0];
    const float* A      = (const float*)d_in[1];
    const float* W      = (const float*)d_in[2];
    const float* attn_a = (const float*)d_in[3];
    const float* bias   = (const float*)d_in[4];
    float* out = (float*)d_out;

    static cudaStream_t s2 = nullptr;
    static cudaEvent_t ev_fork = nullptr, ev_join = nullptr;
    if (s2 == nullptr) {
        cudaFuncSetAttribute(gemm_kernel, cudaFuncAttributeMaxDynamicSharedMemorySize, SMEM_DYN);
        cudaStreamCreateWithFlags(&s2, cudaStreamNonBlocking);
        cudaEventCreateWithFlags(&ev_fork, cudaEventDisableTiming);
        cudaEventCreateWithFlags(&ev_join, cudaEventDisableTiming);
    }

    // fork: adjacency scan (pure DRAM) overlaps the GEMM chain (tensor/smem)
    cudaEventRecord(ev_fork, 0);
    cudaStreamWaitEvent(s2, ev_fork, 0);
    adj_kernel<<<Nn, 256, 0, s2>>>(A);
    cudaEventRecord(ev_join, s2);

    convert_w<<<512, 256>>>(W);
    gemm_kernel<<<dim3(64, 2), 256, SMEM_DYN>>>(X);
    s_kernel<<<4096, 256>>>(attn_a);

    // join: agg needs both adjacency lists and s values
    cudaStreamWaitEvent(0, ev_join, 0);
    agg_kernel<<<Nn, 128>>>(bias, out);
}

// round 8
// speedup vs baseline: 1.3855x; 1.3855x over previous
#include <cuda_runtime.h>
#include <cuda_bf16.h>

#define Nn 8192
#define Ff 1024
#define Fk 64
#define Hh 4
#define Cc 256
#define MAXN 128
#define LEAKY 0.2f

// ---- scratch (static device globals: allocation-free) ----
__device__ float    g_feats[(size_t)Nn * Cc];   // 8 MB
__device__ float    g_ss[Hh * Nn];
__device__ float    g_sn[Hh * Nn];
__device__ int      g_nbr[Nn * MAXN];
__device__ int      g_deg[Nn];
__device__ unsigned g_Whi[(size_t)Cc * Ff / 2]; // W transposed to [n=(h,k)][f], bf16 pairs
__device__ unsigned g_Wlo[(size_t)Cc * Ff / 2];

// ============================================================================
// bf16 hi/lo split helpers
// ============================================================================
__device__ __forceinline__ void split2(float a, float b, unsigned& hi, unsigned& lo) {
    __nv_bfloat16 ha = __float2bfloat16(a), hb = __float2bfloat16(b);
    __nv_bfloat16 la = __float2bfloat16(a - __bfloat162float(ha));
    __nv_bfloat16 lb = __float2bfloat16(b - __bfloat162float(hb));
    hi = (unsigned)__bfloat16_as_ushort(ha) | ((unsigned)__bfloat16_as_ushort(hb) << 16);
    lo = (unsigned)__bfloat16_as_ushort(la) | ((unsigned)__bfloat16_as_ushort(lb) << 16);
}

__global__ __launch_bounds__(256) void convert_w(const float* __restrict__ W) {
    int idx = blockIdx.x * 256 + threadIdx.x;   // 0..131071 = 256 n-rows x 512 pairs
    int n = idx >> 9;
    int f2 = idx & 511;
    int h = n >> 6, k = n & 63;
    const float* base = W + (size_t)h * (Ff * Fk) + k;
    float a = base[(size_t)(2 * f2) * Fk];
    float b = base[(size_t)(2 * f2 + 1) * Fk];
    unsigned hi, lo;
    split2(a, b, hi, lo);
    g_Whi[idx] = hi;
    g_Wlo[idx] = lo;
}

// ============================================================================
// Tensor-core GEMM via mma.sync, with fused s_self/s_neigh epilogue.
// feats[8192 x 256] = X[8192 x 1024] * Wt[1024 x 256], 3-term bf16 split.
// CTA: 128m x 128n, K chunks of 64, 256 thr (8 warps, 4m x 2n), warp 32x64.
// Each warp's 64-col span == one head -> s dots computed from accumulators.
// ============================================================================
#define TP   144           // padded row pitch (bytes) for 64 bf16 = 128B data
#define TSZ  (128 * TP)    // 18432
#define BUFSZ (4 * TSZ)    // 73728
#define SMEM_DYN (2 * BUFSZ)

__device__ __forceinline__ void mma16816(float* d, const unsigned* a, const unsigned* b) {
    asm volatile(
        "mma.sync.aligned.m16n8k16.row.col.f32.bf16.bf16.f32 "
        "{%0,%1,%2,%3}, {%4,%5,%6,%7}, {%8,%9}, {%0,%1,%2,%3};"
        : "+f"(d[0]), "+f"(d[1]), "+f"(d[2]), "+f"(d[3])
        : "r"(a[0]), "r"(a[1]), "r"(a[2]), "r"(a[3]), "r"(b[0]), "r"(b[1]));
}

__global__ __launch_bounds__(256) void gemm_kernel(const float* __restrict__ X,
                                                   const float* __restrict__ attn_a) {
    extern __shared__ char dyn[];
    const int t = threadIdx.x;
    const int w = t >> 5, lane = t & 31;
    const int bm = blockIdx.x * 128;
    const int n0 = blockIdx.y * 128;
    const int mrow = (w & 3) * 32;     // warp m-offset
    const int ncol = (w >> 2) * 64;    // warp n-offset
    const int r  = lane >> 2;          // fragment group row
    const int cb = (lane & 3) * 2;     // fragment k pair base

    float acc[2][8][4];
#pragma unroll
    for (int a = 0; a < 2; a++)
#pragma unroll
        for (int b = 0; b < 8; b++)
#pragma unroll
            for (int q = 0; q < 4; q++) acc[a][b][q] = 0.f;

    const uint4* WhiG = (const uint4*)g_Whi;
    const uint4* WloG = (const uint4*)g_Wlo;

    float4 xr[8];
    uint4  whr[4], wlr[4];

    // ---- prologue: load chunk 0 ----
#pragma unroll
    for (int i = 0; i < 8; i++) {
        int u = t + i * 256, row = u >> 4, j = u & 15;
        xr[i] = *(const float4*)(X + (size_t)(bm + row) * Ff + j * 4);
    }
#pragma unroll
    for (int i = 0; i < 4; i++) {
        int u = t + i * 256, row = u >> 3, j = u & 7;
        size_t g = (size_t)(n0 + row) * 128 + j;
        whr[i] = WhiG[g];
        wlr[i] = WloG[g];
    }
    {
        char* buf = dyn;
#pragma unroll
        for (int i = 0; i < 8; i++) {
            int u = t + i * 256, row = u >> 4, j = u & 15;
            uint2 h, l;
            split2(xr[i].x, xr[i].y, h.x, l.x);
            split2(xr[i].z, xr[i].w, h.y, l.y);
            *(uint2*)(buf + row * TP + j * 8)       = h;
            *(uint2*)(buf + TSZ + row * TP + j * 8) = l;
        }
#pragma unroll
        for (int i = 0; i < 4; i++) {
            int u = t + i * 256, row = u >> 3, j = u & 7;
            *(uint4*)(buf + 2 * TSZ + row * TP + j * 16) = whr[i];
            *(uint4*)(buf + 3 * TSZ + row * TP + j * 16) = wlr[i];
        }
    }
    __syncthreads();

#pragma unroll 1
    for (int c = 0; c < 16; c++) {
        // ---- issue global loads for next chunk ----
        if (c < 15) {
#pragma unroll
            for (int i = 0; i < 8; i++) {
                int u = t + i * 256, row = u >> 4, j = u & 15;
                xr[i] = *(const float4*)(X + (size_t)(bm + row) * Ff + (c + 1) * 64 + j * 4);
            }
#pragma unroll
            for (int i = 0; i < 4; i++) {
                int u = t + i * 256, row = u >> 3, j = u & 7;
                size_t g = (size_t)(n0 + row) * 128 + (c + 1) * 8 + j;
                whr[i] = WhiG[g];
                wlr[i] = WloG[g];
            }
        }

        // ---- mma on current buffer ----
        {
            char* buf = dyn + (c & 1) * BUFSZ;
            char* Ahi = buf;
            char* Alo = buf + TSZ;
            char* Bhi = buf + 2 * TSZ;
            char* Blo = buf + 3 * TSZ;
#pragma unroll
            for (int ks = 0; ks < 4; ks++) {
                unsigned afh[2][4], afl[2][4];   // [mb][reg]
                unsigned bfh[8][2], bfl[8][2];   // [nb][reg]
#pragma unroll
                for (int mb = 0; mb < 2; mb++) {
                    int ab = (mrow + mb * 16 + r) * TP + (ks * 16 + cb) * 2;
                    afh[mb][0] = *(const unsigned*)(Ahi + ab);
                    afh[mb][1] = *(const unsigned*)(Ahi + ab + 8 * TP);
                    afh[mb][2] = *(const unsigned*)(Ahi + ab + 16);
                    afh[mb][3] = *(const unsigned*)(Ahi + ab + 8 * TP + 16);
                    afl[mb][0] = *(const unsigned*)(Alo + ab);
                    afl[mb][1] = *(const unsigned*)(Alo + ab + 8 * TP);
                    afl[mb][2] = *(const unsigned*)(Alo + ab + 16);
                    afl[mb][3] = *(const unsigned*)(Alo + ab + 8 * TP + 16);
                }
#pragma unroll
                for (int nb = 0; nb < 8; nb++) {
                    int bb = (ncol + nb * 8 + r) * TP + (ks * 16 + cb) * 2;
                    bfh[nb][0] = *(const unsigned*)(Bhi + bb);
                    bfh[nb][1] = *(const unsigned*)(Bhi + bb + 16);
                    bfl[nb][0] = *(const unsigned*)(Blo + bb);
                    bfl[nb][1] = *(const unsigned*)(Blo + bb + 16);
                }
#pragma unroll
                for (int mb = 0; mb < 2; mb++)
#pragma unroll
                    for (int nb = 0; nb < 8; nb++) {
                        mma16816(acc[mb][nb], afh[mb], bfh[nb]);
                        mma16816(acc[mb][nb], afh[mb], bfl[nb]);
                        mma16816(acc[mb][nb], afl[mb], bfh[nb]);
                    }
            }
        }

        // ---- store next chunk into other buffer ----
        if (c < 15) {
            char* buf = dyn + ((c + 1) & 1) * BUFSZ;
#pragma unroll
            for (int i = 0; i < 8; i++) {
                int u = t + i * 256, row = u >> 4, j = u & 15;
                uint2 h, l;
                split2(xr[i].x, xr[i].y, h.x, l.x);
                split2(xr[i].z, xr[i].w, h.y, l.y);
                *(uint2*)(buf + row * TP + j * 8)       = h;
                *(uint2*)(buf + TSZ + row * TP + j * 8) = l;
            }
#pragma unroll
            for (int i = 0; i < 4; i++) {
                int u = t + i * 256, row = u >> 3, j = u & 7;
                *(uint4*)(buf + 2 * TSZ + row * TP + j * 16) = whr[i];
                *(uint4*)(buf + 3 * TSZ + row * TP + j * 16) = wlr[i];
            }
            __syncthreads();
        }
    }

    // ---- epilogue 1: write feats ----
#pragma unroll
    for (int mb = 0; mb < 2; mb++) {
        int row0 = bm + mrow + mb * 16 + r;
#pragma unroll
        for (int nb = 0; nb < 8; nb++) {
            int col = n0 + ncol + nb * 8 + cb;
            *(float2*)(g_feats + (size_t)row0 * Cc + col) =
                make_float2(acc[mb][nb][0], acc[mb][nb][1]);
            *(float2*)(g_feats + (size_t)(row0 + 8) * Cc + col) =
                make_float2(acc[mb][nb][2], acc[mb][nb][3]);
        }
    }

    // ---- epilogue 2: fused s_self / s_neigh ----
    // This warp's 64 cols == head (n0+ncol)/64. Per thread: 4 partial row-dots
    // over its 16 cols, then quad reduce (lanes sharing r cover all 64 cols).
    {
        int head = (n0 + ncol) >> 6;
        const float* av = attn_a + head * (2 * Fk);   // [0:64) self, [64:128) neigh
        float ps[4] = {0.f, 0.f, 0.f, 0.f};   // idx = 2*mb + half(rows +0/+8)
        float pn[4] = {0.f, 0.f, 0.f, 0.f};
#pragma unroll
        for (int nb = 0; nb < 8; nb++) {
            int k = nb * 8 + cb;
            float as0 = __ldg(av + k),      as1 = __ldg(av + k + 1);
            float an0 = __ldg(av + 64 + k), an1 = __ldg(av + 64 + k + 1);
#pragma unroll
            for (int mb = 0; mb < 2; mb++) {
                ps[2 * mb + 0] += acc[mb][nb][0] * as0 + acc[mb][nb][1] * as1;
                ps[2 * mb + 1] += acc[mb][nb][2] * as0 + acc[mb][nb][3] * as1;
                pn[2 * mb + 0] += acc[mb][nb][0] * an0 + acc[mb][nb][1] * an1;
                pn[2 * mb + 1] += acc[mb][nb][2] * an0 + acc[mb][nb][3] * an1;
            }
        }
#pragma unroll
        for (int o = 1; o <= 2; o <<= 1) {
#pragma unroll
            for (int i = 0; i < 4; i++) {
                ps[i] += __shfl_xor_sync(0xffffffffu, ps[i], o);
                pn[i] += __shfl_xor_sync(0xffffffffu, pn[i], o);
            }
        }
        if ((lane & 3) == 0) {
#pragma unroll
            for (int i = 0; i < 4; i++) {
                int mb = i >> 1, half = i & 1;
                int row = bm + mrow + mb * 16 + r + half * 8;
                g_ss[head * Nn + row] = ps[i];
                g_sn[head * Nn + row] = pn[i];
            }
        }
    }
}

// ============================================================================
// Adjacency build
// ============================================================================
__global__ __launch_bounds__(256) void adj_kernel(const float* __restrict__ A) {
    int row = blockIdx.x;
    __shared__ int cnt;
    if (threadIdx.x == 0) cnt = 0;
    __syncthreads();
    const float4* ap = (const float4*)(A + (size_t)row * Nn);
    for (int c4 = threadIdx.x; c4 < Nn / 4; c4 += 256) {
        float4 v = ap[c4];
        int base = c4 * 4;
        if (v.x != 0.f) { int p = atomicAdd(&cnt, 1); if (p < MAXN) g_nbr[row * MAXN + p] = base; }
        if (v.y != 0.f) { int p = atomicAdd(&cnt, 1); if (p < MAXN) g_nbr[row * MAXN + p] = base + 1; }
        if (v.z != 0.f) { int p = atomicAdd(&cnt, 1); if (p < MAXN) g_nbr[row * MAXN + p] = base + 2; }
        if (v.w != 0.f) { int p = atomicAdd(&cnt, 1); if (p < MAXN) g_nbr[row * MAXN + p] = base + 3; }
    }
    __syncthreads();
    if (threadIdx.x == 0) g_deg[row] = min(cnt, MAXN);
}

// ============================================================================
// Aggregation: sparse softmax + gather + ReLU
// ============================================================================
__global__ __launch_bounds__(128) void agg_kernel(const float* __restrict__ bias,
                                                  float* __restrict__ out) {
    int i = blockIdx.x;
    int tid = threadIdx.x;
    int h = tid >> 5, lane = tid & 31;
    __shared__ int   snbr[MAXN];
    __shared__ float sw[Hh][MAXN];

    int d = g_deg[i];
    for (int j = tid; j < d; j += 128) snbr[j] = g_nbr[i * MAXN + j];
    __syncthreads();

    float si = g_ss[h * Nn + i];
    float e[4];
    float mx = -1e30f;
#pragma unroll
    for (int r = 0; r < 4; r++) {
        int j = lane + r * 32;
        if (j < d) {
            float sc = si + g_sn[h * Nn + snbr[j]];
            sc = sc > 0.f ? sc : LEAKY * sc;
            e[r] = sc;
            mx = fmaxf(mx, sc);
        } else {
            e[r] = -1e30f;
        }
    }
#pragma unroll
    for (int o = 16; o; o >>= 1) mx = fmaxf(mx, __shfl_xor_sync(0xffffffffu, mx, o));

    float sum = 0.f;
#pragma unroll
    for (int r = 0; r < 4; r++) {
        int j = lane + r * 32;
        if (j < d) {
            float w = __expf(e[r] - mx);
            sw[h][j] = w;
            sum += w;
        }
    }
#pragma unroll
    for (int o = 16; o; o >>= 1) sum += __shfl_xor_sync(0xffffffffu, sum, o);
    __syncwarp();

    float inv = 1.0f / sum;
    float acc0 = 0.f, acc1 = 0.f;
    int j = 0;
    for (; j + 2 <= d; j += 2) {
        float w0 = sw[h][j], w1 = sw[h][j + 1];
        const float* f0 = g_feats + (size_t)snbr[j] * Cc + h * Fk;
        const float* f1 = g_feats + (size_t)snbr[j + 1] * Cc + h * Fk;
        float a00 = f0[lane], a01 = f0[lane + 32];
        float a10 = f1[lane], a11 = f1[lane + 32];
        acc0 += w0 * a00 + w1 * a10;
        acc1 += w0 * a01 + w1 * a11;
    }
    if (j < d) {
        float w0 = sw[h][j];
        const float* f0 = g_feats + (size_t)snbr[j] * Cc + h * Fk;
        acc0 += w0 * f0[lane];
        acc1 += w0 * f0[lane + 32];
    }
    float b0 = bias[h * Fk + lane];
    float b1 = bias[h * Fk + lane + 32];
    out[(size_t)i * Cc + h * Fk + lane]      = fmaxf(acc0 * inv + b0, 0.f);
    out[(size_t)i * Cc + h * Fk + lane + 32] = fmaxf(acc1 * inv + b1, 0.f);
}

// ============================================================================
extern "C" void kernel_launch(void* const* d_in, const int* in_sizes, int n_in,
                              void* d_out, int out_size) {
    const float* X      = (const float*)d_in[0];
    const float* A      = (const float*)d_in[1];
    const float* W      = (const float*)d_in[2];
    const float* attn_a = (const float*)d_in[3];
    const float* bias   = (const float*)d_in[4];
    float* out = (float*)d_out;

    static int smem_set = 0;
    if (!smem_set) {
        cudaFuncSetAttribute(gemm_kernel, cudaFuncAttributeMaxDynamicSharedMemorySize, SMEM_DYN);
        smem_set = 1;
    }

    convert_w<<<512, 256>>>(W);
    gemm_kernel<<<dim3(64, 2), 256, SMEM_DYN>>>(X, attn_a);
    adj_kernel<<<Nn, 256>>>(A);
    agg_kernel<<<Nn, 128>>>(bias, out);
}